// round 1
// baseline (speedup 1.0000x reference)
#include <cuda_runtime.h>
#include <cuda_bf16.h>

// Fixed problem shapes (registry problem is shape-deduped):
//   tex (8,16,512,512) f32, iuv (8,3,512,512) i32, lut (24,256,256,2) f32,
//   tex_res = 512 (1-element i32 device scalar), out (8,16,512,512) f32.
#define BB 8
#define CC 16
#define RR 512
#define RR2 (RR * RR)        // 262144 = 2^18
#define HW  (512 * 512)      // 2^18
#define LOG2_RR2 18
#define LOG2_HW  18

// Scratch: tex transposed to [b][p][c] so one pixel's 16 channels are
// 64 contiguous bytes (2 fully-used 32B sectors per gather).
__device__ float g_tex_trans[(size_t)BB * RR2 * CC];

// ---------------------------------------------------------------------------
// Transpose (B,C,R,R) -> (B,R*R,C). Each thread emits one float4 =
// 4 channels of one pixel. Reads: per channel, 8 lanes of a warp read
// consecutive pixels (coalesced). Writes: warp writes 512 contiguous bytes.
// ---------------------------------------------------------------------------
__global__ void __launch_bounds__(256) transpose_kernel(const float* __restrict__ tex) {
    int idx = blockIdx.x * blockDim.x + threadIdx.x;   // [0, B*RR2*4)
    int c4 = idx & 3;                                   // channel group 0..3
    int p  = (idx >> 2) & (RR2 - 1);                    // pixel in batch
    int b  = idx >> (2 + LOG2_RR2);                     // batch

    const float* src = tex + ((size_t)b * CC + (size_t)c4 * 4) * RR2 + p;
    float4 v;
    v.x = __ldg(src + 0 * RR2);
    v.y = __ldg(src + 1 * RR2);
    v.z = __ldg(src + 2 * RR2);
    v.w = __ldg(src + 3 * RR2);

    reinterpret_cast<float4*>(g_tex_trans)[idx] = v;
}

// ---------------------------------------------------------------------------
// Main kernel: one thread per (b, pixel).
// ---------------------------------------------------------------------------
__global__ void __launch_bounds__(256) densepose_kernel(
    const int* __restrict__ iuv,
    const float* __restrict__ lut,
    const int* __restrict__ tex_res_ptr,
    float* __restrict__ out)
{
    int idx = blockIdx.x * blockDim.x + threadIdx.x;   // [0, B*HW)
    int pix = idx & (HW - 1);
    int b   = idx >> LOG2_HW;

    const int* iuvb = iuv + (size_t)b * 3 * HW + pix;
    int part = iuvb[0];

    float4 r0 = make_float4(0.f, 0.f, 0.f, 0.f);
    float4 r1 = r0, r2 = r0, r3 = r0;

    if (part > 0) {
        int u8 = iuvb[1 * HW];
        int v8 = iuvb[2 * HW];

        int i = min(max(part - 1, 0), 23);

        // Replicate reference float math exactly (round = rn = half-to-even).
        float uf = fminf(fmaxf((float)u8 * (1.0f / 255.0f), 0.0f), 1.0f);
        float vf = fminf(fmaxf((float)v8 * (1.0f / 255.0f), 0.0f), 1.0f);
        int ui = __float2int_rn(uf * 255.0f);
        int vi = __float2int_rn(vf * 255.0f);

        float2 uv = __ldg(reinterpret_cast<const float2*>(lut)
                          + ((size_t)i * 256 + vi) * 256 + ui);

        float res_m1 = (float)(__ldg(tex_res_ptr) - 1);
        int u_I = __float2int_rn(uv.x * res_m1);
        int v_I = __float2int_rn((1.0f - uv.y) * res_m1);
        // jax clamps OOB indices; be exact.
        u_I = min(max(u_I, 0), RR - 1);
        v_I = min(max(v_I, 0), RR - 1);

        const float4* src = reinterpret_cast<const float4*>(g_tex_trans)
                          + ((size_t)b * RR2 + (size_t)v_I * RR + u_I) * 4;
        r0 = __ldg(src + 0);
        r1 = __ldg(src + 1);
        r2 = __ldg(src + 2);
        r3 = __ldg(src + 3);
    }

    // Output (B,C,H,W): per channel, consecutive threads write consecutive w
    // -> each of the 16 stores is fully coalesced.
    float* o = out + (size_t)b * CC * HW + pix;
    o[ 0 * HW] = r0.x;  o[ 1 * HW] = r0.y;  o[ 2 * HW] = r0.z;  o[ 3 * HW] = r0.w;
    o[ 4 * HW] = r1.x;  o[ 5 * HW] = r1.y;  o[ 6 * HW] = r1.z;  o[ 7 * HW] = r1.w;
    o[ 8 * HW] = r2.x;  o[ 9 * HW] = r2.y;  o[10 * HW] = r2.z;  o[11 * HW] = r2.w;
    o[12 * HW] = r3.x;  o[13 * HW] = r3.y;  o[14 * HW] = r3.z;  o[15 * HW] = r3.w;
}

extern "C" void kernel_launch(void* const* d_in, const int* in_sizes, int n_in,
                              void* d_out, int out_size)
{
    const float* tex     = (const float*)d_in[0];
    const int*   iuv     = (const int*)  d_in[1];
    const float* lut     = (const float*)d_in[2];
    const int*   tex_res = (const int*)  d_in[3];
    float* out = (float*)d_out;

    // Transpose: B*RR2*4 float4-threads
    {
        int total = BB * RR2 * 4;          // 8,388,608
        transpose_kernel<<<total / 256, 256>>>(tex);
    }
    // Main: B*HW threads
    {
        int total = BB * HW;               // 2,097,152
        densepose_kernel<<<total / 256, 256>>>(iuv, lut, tex_res, out);
    }
}

// round 2
// speedup vs baseline: 1.0159x; 1.0159x over previous
#include <cuda_runtime.h>
#include <cuda_bf16.h>

// Fixed problem shapes:
//   tex (8,16,512,512) f32, iuv (8,3,512,512) i32, lut (24,256,256,2) f32,
//   tex_res = 512 (1-element i32 device scalar), out (8,16,512,512) f32.
#define BB 8
#define CC 16
#define RR 512
#define RR2 (RR * RR)        // 262144 = 2^18
#define HW  (512 * 512)      // 2^18
#define LOG2_RR2 18
#define LOG2_HW  18
#define NB 2                 // batches per chunk (scratch = 32 MiB, L2-resident)

// Reused per-chunk scratch: tex transposed to [bl][p][c]. 32 MiB — fits in the
// 126 MB L2 alongside the streaming traffic, so it should never be written to
// or re-read from DRAM. All stream-once traffic uses evict-first hints (.cs)
// so L2 keeps these lines hot.
__device__ float g_scratch[(size_t)NB * RR2 * CC];

// ---------------------------------------------------------------------------
// Transpose chunk: (NB,C,R,R) slice of tex -> scratch (NB,R*R,C).
// Each thread emits one float4 = 4 channels of one pixel.
// tex reads are stream-once -> __ldcs (evict-first in L2).
// scratch writes are normal (write-allocate, keep in L2).
// ---------------------------------------------------------------------------
__global__ void __launch_bounds__(256) transpose_kernel(
    const float* __restrict__ tex, int b0)
{
    int idx = blockIdx.x * blockDim.x + threadIdx.x;   // [0, NB*RR2*4)
    int c4 = idx & 3;                                   // channel group 0..3
    int p  = (idx >> 2) & (RR2 - 1);                    // pixel in batch
    int bl = idx >> (2 + LOG2_RR2);                     // local batch 0..NB-1
    int b  = b0 + bl;

    const float* src = tex + ((size_t)b * CC + (size_t)c4 * 4) * RR2 + p;
    float4 v;
    v.x = __ldcs(src + 0 * RR2);
    v.y = __ldcs(src + 1 * RR2);
    v.z = __ldcs(src + 2 * RR2);
    v.w = __ldcs(src + 3 * RR2);

    reinterpret_cast<float4*>(g_scratch)[idx] = v;
}

// ---------------------------------------------------------------------------
// Gather chunk: one thread per (local batch, pixel). Gathers a pixel's 16
// channels as 64 contiguous bytes from the (L2-hot) scratch.
// iuv reads + out writes are stream-once -> .cs hints.
// ---------------------------------------------------------------------------
__global__ void __launch_bounds__(256) densepose_kernel(
    const int* __restrict__ iuv,
    const float* __restrict__ lut,
    const int* __restrict__ tex_res_ptr,
    float* __restrict__ out, int b0)
{
    int idx = blockIdx.x * blockDim.x + threadIdx.x;   // [0, NB*HW)
    int pix = idx & (HW - 1);
    int bl  = idx >> LOG2_HW;                           // local batch 0..NB-1
    int b   = b0 + bl;

    const int* iuvb = iuv + (size_t)b * 3 * HW + pix;
    int part = __ldcs(iuvb);

    float4 r0 = make_float4(0.f, 0.f, 0.f, 0.f);
    float4 r1 = r0, r2 = r0, r3 = r0;

    if (part > 0) {
        int u8 = __ldcs(iuvb + 1 * HW);
        int v8 = __ldcs(iuvb + 2 * HW);

        int i = min(max(part - 1, 0), 23);

        // Replicate reference float math exactly (round = rn = half-to-even).
        float uf = fminf(fmaxf((float)u8 * (1.0f / 255.0f), 0.0f), 1.0f);
        float vf = fminf(fmaxf((float)v8 * (1.0f / 255.0f), 0.0f), 1.0f);
        int ui = __float2int_rn(uf * 255.0f);
        int vi = __float2int_rn(vf * 255.0f);

        float2 uv = __ldg(reinterpret_cast<const float2*>(lut)
                          + ((size_t)i * 256 + vi) * 256 + ui);

        float res_m1 = (float)(__ldg(tex_res_ptr) - 1);
        int u_I = __float2int_rn(uv.x * res_m1);
        int v_I = __float2int_rn((1.0f - uv.y) * res_m1);
        // jax clamps OOB indices; be exact.
        u_I = min(max(u_I, 0), RR - 1);
        v_I = min(max(v_I, 0), RR - 1);

        const float4* src = reinterpret_cast<const float4*>(g_scratch)
                          + ((size_t)bl * RR2 + (size_t)v_I * RR + u_I) * 4;
        r0 = __ldg(src + 0);
        r1 = __ldg(src + 1);
        r2 = __ldg(src + 2);
        r3 = __ldg(src + 3);
    }

    // Output (B,C,H,W): per channel, consecutive threads write consecutive w
    // -> each of the 16 stores is fully coalesced. Stream-once -> .cs.
    float* o = out + (size_t)b * CC * HW + pix;
    __stcs(o +  0 * HW, r0.x);  __stcs(o +  1 * HW, r0.y);
    __stcs(o +  2 * HW, r0.z);  __stcs(o +  3 * HW, r0.w);
    __stcs(o +  4 * HW, r1.x);  __stcs(o +  5 * HW, r1.y);
    __stcs(o +  6 * HW, r1.z);  __stcs(o +  7 * HW, r1.w);
    __stcs(o +  8 * HW, r2.x);  __stcs(o +  9 * HW, r2.y);
    __stcs(o + 10 * HW, r2.z);  __stcs(o + 11 * HW, r2.w);
    __stcs(o + 12 * HW, r3.x);  __stcs(o + 13 * HW, r3.y);
    __stcs(o + 14 * HW, r3.z);  __stcs(o + 15 * HW, r3.w);
}

extern "C" void kernel_launch(void* const* d_in, const int* in_sizes, int n_in,
                              void* d_out, int out_size)
{
    const float* tex     = (const float*)d_in[0];
    const int*   iuv     = (const int*)  d_in[1];
    const float* lut     = (const float*)d_in[2];
    const int*   tex_res = (const int*)  d_in[3];
    float* out = (float*)d_out;

    for (int b0 = 0; b0 < BB; b0 += NB) {
        // Transpose: NB*RR2*4 float4-threads
        transpose_kernel<<<(NB * RR2 * 4) / 256, 256>>>(tex, b0);
        // Gather: NB*HW threads
        densepose_kernel<<<(NB * HW) / 256, 256>>>(iuv, lut, tex_res, out, b0);
    }
}